// round 1
// baseline (speedup 1.0000x reference)
#include <cuda_runtime.h>
#include <math.h>

#define NN   50000
#define EE   800000
#define DIN  128
#define D1   150
#define D2   100
#define DOUT 64
#define SCAN_B ((NN + 1023) / 1024)

// ---------------- scratch (static device globals; no allocation) ----------------
__device__ float g_deg_out[NN];
__device__ int   g_deg_in[NN];
__device__ int   g_off[NN + 1];
__device__ int   g_cur[NN];
__device__ int   g_bsum[SCAN_B];
__device__ int   g_bsum2[SCAN_B];
__device__ int   g_csr[EE];
__device__ float g_norm_out[NN];
__device__ float g_norm_in[NN];
__device__ float g_invdeg[NN];
__device__ float g_agg[(size_t)NN * DIN];
__device__ float g_h1[(size_t)NN * D1];
__device__ float g_neigh[(size_t)NN * D1];
__device__ float g_h2[(size_t)NN * D2];

__device__ __forceinline__ float elu_f(float v) { return v > 0.f ? v : expm1f(v); }

// ---------------- graph preprocessing ----------------
__global__ void k_zero() {
    int i = blockIdx.x * blockDim.x + threadIdx.x;
    if (i < NN) { g_deg_out[i] = 0.f; g_deg_in[i] = 0; g_cur[i] = 0; }
}

__global__ void k_degrees(const int* __restrict__ src, const int* __restrict__ dst) {
    int e = blockIdx.x * blockDim.x + threadIdx.x;
    if (e >= EE) return;
    atomicAdd(&g_deg_out[src[e]], 1.f);
    atomicAdd(&g_deg_in[dst[e]], 1);
}

__global__ void k_norms() {
    int i = blockIdx.x * blockDim.x + threadIdx.x;
    if (i >= NN) return;
    float dof = g_deg_out[i];
    g_norm_out[i] = rsqrtf(fmaxf(dof, 1.f));
    float din = (float)g_deg_in[i];
    float dmx = fmaxf(din, 1.f);
    g_norm_in[i] = rsqrtf(dmx);
    g_invdeg[i]  = 1.f / dmx;
}

// inclusive scan per 1024-block of deg_in -> g_off[i+1], block totals -> g_bsum
__global__ void k_scan1() {
    __shared__ int s[1024];
    int tid = threadIdx.x;
    int i = blockIdx.x * 1024 + tid;
    int v = (i < NN) ? g_deg_in[i] : 0;
    s[tid] = v;
    __syncthreads();
    for (int off = 1; off < 1024; off <<= 1) {
        int t = (tid >= off) ? s[tid - off] : 0;
        __syncthreads();
        s[tid] += t;
        __syncthreads();
    }
    if (i < NN) g_off[i + 1] = s[tid];
    if (tid == 1023) g_bsum[blockIdx.x] = s[1023];
}

__global__ void k_scan2() {  // exclusive scan of SCAN_B block sums (tiny, serial)
    if (threadIdx.x == 0 && blockIdx.x == 0) {
        int acc = 0;
        for (int b = 0; b < SCAN_B; b++) { g_bsum2[b] = acc; acc += g_bsum[b]; }
    }
}

__global__ void k_scan3() {
    int tid = threadIdx.x;
    int i = blockIdx.x * 1024 + tid;
    if (i < NN && blockIdx.x > 0) g_off[i + 1] += g_bsum2[blockIdx.x];
    if (i == 0) g_off[0] = 0;
}

__global__ void k_fill(const int* __restrict__ src, const int* __restrict__ dst) {
    int e = blockIdx.x * blockDim.x + threadIdx.x;
    if (e >= EE) return;
    int d = dst[e];
    int p = atomicAdd(&g_cur[d], 1);
    g_csr[g_off[d] + p] = src[e];
}

// ---------------- aggregation (pull mode, 1 warp / node) ----------------
__global__ void k_agg1(const float* __restrict__ x) {
    int w    = (blockIdx.x * blockDim.x + threadIdx.x) >> 5;
    int lane = threadIdx.x & 31;
    if (w >= NN) return;
    int beg = g_off[w], end = g_off[w + 1];
    const float4* X = (const float4*)x;
    float4 acc = make_float4(0.f, 0.f, 0.f, 0.f);
    int j = beg;
    for (; j + 1 < end; j += 2) {
        int s0 = g_csr[j], s1 = g_csr[j + 1];
        float w0 = g_norm_out[s0], w1 = g_norm_out[s1];
        float4 v0 = X[(size_t)s0 * 32 + lane];
        float4 v1 = X[(size_t)s1 * 32 + lane];
        acc.x += v0.x * w0 + v1.x * w1;
        acc.y += v0.y * w0 + v1.y * w1;
        acc.z += v0.z * w0 + v1.z * w1;
        acc.w += v0.w * w0 + v1.w * w1;
    }
    if (j < end) {
        int s0 = g_csr[j];
        float w0 = g_norm_out[s0];
        float4 v0 = X[(size_t)s0 * 32 + lane];
        acc.x += v0.x * w0; acc.y += v0.y * w0; acc.z += v0.z * w0; acc.w += v0.w * w0;
    }
    float ni = g_norm_in[w];
    acc.x *= ni; acc.y *= ni; acc.z *= ni; acc.w *= ni;
    ((float4*)g_agg)[(size_t)w * 32 + lane] = acc;
}

__global__ void k_agg2() {
    int w    = (blockIdx.x * blockDim.x + threadIdx.x) >> 5;
    int lane = threadIdx.x & 31;
    if (w >= NN) return;
    int beg = g_off[w], end = g_off[w + 1];
    float acc[5] = {0.f, 0.f, 0.f, 0.f, 0.f};
    for (int j = beg; j < end; j++) {
        int s = g_csr[j];
        const float* r = g_h1 + (size_t)s * D1;
        acc[0] += r[lane];
        acc[1] += r[lane + 32];
        acc[2] += r[lane + 64];
        acc[3] += r[lane + 96];
        if (lane < D1 - 128) acc[4] += r[lane + 128];
    }
    float inv = g_invdeg[w];
    float* o = g_neigh + (size_t)w * D1;
    o[lane]       = acc[0] * inv;
    o[lane + 32]  = acc[1] * inv;
    o[lane + 64]  = acc[2] * inv;
    o[lane + 96]  = acc[3] * inv;
    if (lane < D1 - 128) o[lane + 128] = acc[4] * inv;
}

// ---------------- generic fp32 GEMM with optional concat-K, bias + ELU ----------------
// C[M,N] = elu( A1[M,K1] @ B1[K1,N] (+ A2[M,K2] @ B2[K2,N]) + bias[N] )
__device__ __forceinline__ void gemm_body(
    const float* __restrict__ A1, int K1, const float* __restrict__ B1,
    const float* __restrict__ A2, int K2, const float* __restrict__ B2,
    const float* __restrict__ bias, float* __restrict__ C, int M, int N)
{
    __shared__ float As[16][68];
    __shared__ float Bs[16][64];
    int t  = threadIdx.x;
    int tx = t & 15, ty = t >> 4;
    int m0 = blockIdx.y * 64, n0 = blockIdx.x * 64;

    float acc[4][4];
#pragma unroll
    for (int i = 0; i < 4; i++)
#pragma unroll
        for (int j = 0; j < 4; j++) acc[i][j] = 0.f;

    int nph = (A2 != nullptr) ? 2 : 1;
    for (int ph = 0; ph < nph; ph++) {
        const float* A = (ph == 0) ? A1 : A2;
        const float* B = (ph == 0) ? B1 : B2;
        int K = (ph == 0) ? K1 : K2;
        for (int k0 = 0; k0 < K; k0 += 16) {
#pragma unroll
            for (int i = 0; i < 4; i++) {
                int idx = t + 256 * i;          // 0..1023
                int kk = idx & 15, mm = idx >> 4;
                int gm = m0 + mm, gk = k0 + kk;
                As[kk][mm] = (gm < M && gk < K) ? A[(size_t)gm * K + gk] : 0.f;
            }
#pragma unroll
            for (int i = 0; i < 4; i++) {
                int idx = t + 256 * i;
                int nn = idx & 63, kk = idx >> 6;
                int gk = k0 + kk, gn = n0 + nn;
                Bs[kk][nn] = (gk < K && gn < N) ? B[(size_t)gk * N + gn] : 0.f;
            }
            __syncthreads();
#pragma unroll
            for (int kk = 0; kk < 16; kk++) {
                float4 a = *(const float4*)&As[kk][ty * 4];
                float4 b = *(const float4*)&Bs[kk][tx * 4];
                float av[4] = {a.x, a.y, a.z, a.w};
                float bv[4] = {b.x, b.y, b.z, b.w};
#pragma unroll
                for (int i = 0; i < 4; i++)
#pragma unroll
                    for (int j = 0; j < 4; j++) acc[i][j] += av[i] * bv[j];
            }
            __syncthreads();
        }
    }

#pragma unroll
    for (int i = 0; i < 4; i++) {
        int gm = m0 + ty * 4 + i;
        if (gm >= M) continue;
#pragma unroll
        for (int j = 0; j < 4; j++) {
            int gn = n0 + tx * 4 + j;
            if (gn >= N) continue;
            float v = acc[i][j] + bias[gn];
            C[(size_t)gm * N + gn] = elu_f(v);
        }
    }
}

__global__ void k_gemm1(const float* __restrict__ W1, const float* __restrict__ b1) {
    gemm_body(g_agg, DIN, W1, nullptr, 0, nullptr, b1, g_h1, NN, D1);
}
__global__ void k_gemm2(const float* __restrict__ Ws, const float* __restrict__ Wn,
                        const float* __restrict__ b2) {
    gemm_body(g_h1, D1, Ws, g_neigh, D1, Wn, b2, g_h2, NN, D2);
}
__global__ void k_gemm3(const float* __restrict__ W3, const float* __restrict__ b3,
                        float* __restrict__ out) {
    gemm_body(g_h2, D2, W3, nullptr, 0, nullptr, b3, out, NN, DOUT);
}

// ---------------- launch ----------------
extern "C" void kernel_launch(void* const* d_in, const int* in_sizes, int n_in,
                              void* d_out, int out_size) {
    const float* x   = (const float*)d_in[0];
    const int*   src = (const int*)d_in[1];
    const int*   dst = (const int*)d_in[2];
    const float* W1  = (const float*)d_in[3];
    const float* b1  = (const float*)d_in[4];
    const float* Wn  = (const float*)d_in[5];
    const float* Ws  = (const float*)d_in[6];
    const float* b2  = (const float*)d_in[7];
    const float* W3  = (const float*)d_in[8];
    const float* b3  = (const float*)d_in[9];
    float* out = (float*)d_out;

    k_zero<<<(NN + 255) / 256, 256>>>();
    k_degrees<<<(EE + 255) / 256, 256>>>(src, dst);
    k_norms<<<(NN + 255) / 256, 256>>>();
    k_scan1<<<SCAN_B, 1024>>>();
    k_scan2<<<1, 32>>>();
    k_scan3<<<SCAN_B, 1024>>>();
    k_fill<<<(EE + 255) / 256, 256>>>(src, dst);

    int agg_blocks = (NN * 32 + 255) / 256;
    k_agg1<<<agg_blocks, 256>>>(x);

    dim3 g1((D1 + 63) / 64, (NN + 63) / 64);
    k_gemm1<<<g1, 256>>>(W1, b1);

    k_agg2<<<agg_blocks, 256>>>();

    dim3 g2((D2 + 63) / 64, (NN + 63) / 64);
    k_gemm2<<<g2, 256>>>(Ws, Wn, b2);

    dim3 g3((DOUT + 63) / 64, (NN + 63) / 64);
    k_gemm3<<<g3, 256>>>(W3, b3, out);
}